// round 3
// baseline (speedup 1.0000x reference)
#include <cuda_runtime.h>
#include <math.h>

#define NN 100000
#define EE 1200000
#define GG 128

// ---------------- device scratch (no allocations allowed) ----------------
__device__ float g_bufA[NN * 64];
__device__ float g_bufB[NN * 64];
__device__ int   g_counts[NN];        // degree incl. self loop
__device__ int   g_counter[NN];
__device__ int   g_ptr[NN];           // CSR row start
__device__ int   g_csr[EE + NN];      // src ids bucketed by dst
__device__ int   g_bsums[512];
__device__ float g_dinv[NN];
__device__ float g_bnsum[64];
__device__ float g_bnsq[64];
__device__ float g_scale[64];
__device__ float g_shift[64];
__device__ float g_Wc[64 * 64];
__device__ float g_bc[64];

// packed fp32x2 FMA (Blackwell)
__device__ __forceinline__ float2 ffma2(float2 a, float2 b, float2 c) {
    float2 d;
    asm("{\n\t"
        ".reg .b64 ra, rb, rc;\n\t"
        "mov.b64 ra, {%2, %3};\n\t"
        "mov.b64 rb, {%4, %5};\n\t"
        "mov.b64 rc, {%6, %7};\n\t"
        "fma.rn.f32x2 rc, ra, rb, rc;\n\t"
        "mov.b64 {%0, %1}, rc;\n\t"
        "}"
        : "=f"(d.x), "=f"(d.y)
        : "f"(a.x), "f"(a.y), "f"(b.x), "f"(b.y), "f"(c.x), "f"(c.y));
    return d;
}

// ---------------- CSR build ----------------
__global__ void k_init() {
    int i = blockIdx.x * 256 + threadIdx.x;
    if (i < NN) { g_counts[i] = 1; g_counter[i] = 0; }  // 1 = self loop
}

__global__ void k_hist(const int* __restrict__ ei) {
    int i = blockIdx.x * 256 + threadIdx.x;
    if (i < EE) atomicAdd(&g_counts[ei[EE + i]], 1);
}

__device__ __forceinline__ int warp_incl(int v, int lane) {
    #pragma unroll
    for (int o = 1; o < 32; o <<= 1) {
        int t = __shfl_up_sync(0xFFFFFFFFu, v, o);
        if (lane >= o) v += t;
    }
    return v;
}

template <int NW>
__device__ __forceinline__ int block_excl_scan(int v, int tid, int* total) {
    __shared__ int wt[NW];
    int lane = tid & 31, wid = tid >> 5;
    int incl = warp_incl(v, lane);
    if (lane == 31) wt[wid] = incl;
    __syncthreads();
    if (wid == 0) {
        int x = (lane < NW) ? wt[lane] : 0;
        x = warp_incl(x, lane);
        if (lane < NW) wt[lane] = x;
    }
    __syncthreads();
    int off = wid ? wt[wid - 1] : 0;
    *total = wt[NW - 1];
    return off + incl - v;
}

__global__ void k_scan1() {
    int tid = threadIdx.x;
    int i = blockIdx.x * 256 + tid;
    int v = (i < NN) ? g_counts[i] : 0;
    if (i < NN) g_dinv[i] = rsqrtf((float)v);
    int total;
    int e = block_excl_scan<8>(v, tid, &total);
    if (i < NN) g_ptr[i] = e;
    if (tid == 0) g_bsums[blockIdx.x] = total;
}

__global__ void k_scan2(int nb) {
    int tid = threadIdx.x;
    int v = (tid < nb) ? g_bsums[tid] : 0;
    int total;
    int e = block_excl_scan<16>(v, tid, &total);
    if (tid < nb) g_bsums[tid] = e;
}

__global__ void k_scan3() {
    int i = blockIdx.x * 256 + threadIdx.x;
    if (i < NN) g_ptr[i] += g_bsums[blockIdx.x];
}

__global__ void k_fill(const int* __restrict__ ei) {
    int i = blockIdx.x * 256 + threadIdx.x;
    if (i < EE) {
        int d = ei[EE + i];
        int pos = g_ptr[d] + atomicAdd(&g_counter[d], 1);
        g_csr[pos] = ei[i];
    }
}

// ------ GEMM: bufB = act(hin) @ W (+bias) [optionally * dinv[row]] ------
// act (BN scale/shift + relu) fused on load; dinv scaling fused on store.
__global__ __launch_bounds__(256) void k_gemm(
    const float* __restrict__ xin,   // used when src0 != 0
    const float* __restrict__ Wext,  // used when use_wc == 0
    int src0, int use_wc, int use_act, int scale_dinv,
    float* __restrict__ emb_out)     // optional: write activated input rows
{
    const float* hin = src0 ? xin : g_bufA;
    const float* W   = use_wc ? g_Wc : Wext;
    float*       out = g_bufB;

    int j  = threadIdx.x;   // feature/col 0..63
    int ty = threadIdx.y;   // 0..3 rows per iter

    float2 wcol[32];        // W column j, paired over k
    #pragma unroll
    for (int k2 = 0; k2 < 32; k2++)
        wcol[k2] = make_float2(W[(2 * k2) * 64 + j], W[(2 * k2 + 1) * 64 + j]);

    float sc = 1.f, sh = 0.f;
    if (use_act) { sc = g_scale[j]; sh = g_shift[j]; }
    float b = use_wc ? g_bc[j] : 0.f;

    __shared__ float rows[4][64];
    for (int r0 = blockIdx.x * 4; r0 < NN; r0 += gridDim.x * 4) {
        int r = r0 + ty;                       // NN % 4 == 0 -> always valid
        float v = hin[r * 64 + j];
        if (use_act) v = fmaxf(v * sc + sh, 0.f);
        rows[ty][j] = v;
        if (emb_out) emb_out[r * 64 + j] = v;
        __syncthreads();
        const float2* rp = reinterpret_cast<const float2*>(rows[ty]);
        float2 acc = make_float2(0.f, 0.f);
        #pragma unroll
        for (int k2 = 0; k2 < 32; k2++)
            acc = ffma2(rp[k2], wcol[k2], acc);
        float res = acc.x + acc.y + b;
        if (scale_dinv) res *= g_dinv[r];
        out[r * 64 + j] = res;
        __syncthreads();
    }
}

// ---- aggregation: bufA = dinv[d] * (sum_{s in N(d)} hS[s] + hS[d]) + bias ----
// where hS = dinv-prescaled conv output (bufB). BN stats fused.
__global__ __launch_bounds__(256) void k_agg(const float* __restrict__ bias) {
    int lane = threadIdx.x & 31, wid = threadIdx.x >> 5;
    int w  = blockIdx.x * 8 + wid;
    int nw = gridDim.x * 8;
    const float2* h2 = reinterpret_cast<const float2*>(g_bufB);
    float2* ao = reinterpret_cast<float2*>(g_bufA);
    float2 b2 = reinterpret_cast<const float2*>(bias)[lane];
    float2 psum = make_float2(0.f, 0.f), psq = make_float2(0.f, 0.f);

    for (int node = w; node < NN; node += nw) {
        int beg = g_ptr[node];
        int cnt = g_counts[node] - 1;          // real (non-self) edges
        float di = g_dinv[node];
        float2 acc0 = make_float2(0.f, 0.f);
        float2 acc1 = make_float2(0.f, 0.f);
        float2 acc2 = make_float2(0.f, 0.f);
        float2 acc3 = make_float2(0.f, 0.f);
        int t = 0;
        // unroll x4 for memory-level parallelism on the gather chain
        for (; t + 4 <= cnt; t += 4) {
            int s0 = g_csr[beg + t];
            int s1 = g_csr[beg + t + 1];
            int s2 = g_csr[beg + t + 2];
            int s3 = g_csr[beg + t + 3];
            float2 v0 = h2[s0 * 32 + lane];
            float2 v1 = h2[s1 * 32 + lane];
            float2 v2 = h2[s2 * 32 + lane];
            float2 v3 = h2[s3 * 32 + lane];
            acc0.x += v0.x; acc0.y += v0.y;
            acc1.x += v1.x; acc1.y += v1.y;
            acc2.x += v2.x; acc2.y += v2.y;
            acc3.x += v3.x; acc3.y += v3.y;
        }
        for (; t < cnt; t++) {
            int s0 = g_csr[beg + t];
            float2 v0 = h2[s0 * 32 + lane];
            acc0.x += v0.x; acc0.y += v0.y;
        }
        float2 hs = h2[node * 32 + lane];      // self term (pre-scaled)
        acc0.x += acc2.x; acc0.y += acc2.y;
        acc1.x += acc3.x; acc1.y += acc3.y;
        acc0.x += acc1.x + hs.x;
        acc0.y += acc1.y + hs.y;
        acc0.x = di * acc0.x + b2.x;
        acc0.y = di * acc0.y + b2.y;
        ao[node * 32 + lane] = acc0;
        psum.x += acc0.x; psum.y += acc0.y;
        psq.x += acc0.x * acc0.x; psq.y += acc0.y * acc0.y;
    }

    __shared__ float ssum[64], ssq[64];
    if (threadIdx.x < 64) { ssum[threadIdx.x] = 0.f; ssq[threadIdx.x] = 0.f; }
    __syncthreads();
    atomicAdd(&ssum[2 * lane],     psum.x);
    atomicAdd(&ssum[2 * lane + 1], psum.y);
    atomicAdd(&ssq[2 * lane],      psq.x);
    atomicAdd(&ssq[2 * lane + 1],  psq.y);
    __syncthreads();
    if (threadIdx.x < 64) {
        atomicAdd(&g_bnsum[threadIdx.x], ssum[threadIdx.x]);
        atomicAdd(&g_bnsq[threadIdx.x],  ssq[threadIdx.x]);
    }
}

__global__ void k_bnzero() {
    if (threadIdx.x < 64) { g_bnsum[threadIdx.x] = 0.f; g_bnsq[threadIdx.x] = 0.f; }
}

__global__ void k_bnfinal(const float* __restrict__ gma, const float* __restrict__ bta) {
    int f = threadIdx.x;
    if (f < 64) {
        float mu  = g_bnsum[f] * (1.0f / NN);
        float var = g_bnsq[f] * (1.0f / NN) - mu * mu;
        float istd = rsqrtf(var + 1e-5f);
        float s = istd * gma[f];
        g_scale[f] = s;
        g_shift[f] = bta[f] - mu * s;
    }
}

// ---------------- Wc = fc1_w @ fc2_w ; bc = fc1_b @ fc2_w + fc2_b ----------------
__global__ void k_combine(const float* __restrict__ fc1w, const float* __restrict__ fc1b,
                          const float* __restrict__ fc2w, const float* __restrict__ fc2b) {
    int idx = blockIdx.x * 256 + threadIdx.x;
    if (idx < 4096) {
        int k = idx >> 6, j = idx & 63;
        float s = 0.f;
        #pragma unroll
        for (int t = 0; t < 64; t++) s += fc1w[k * 64 + t] * fc2w[t * 64 + j];
        g_Wc[idx] = s;
    }
    if (idx < 64) {
        float s = fc2b[idx];
        for (int t = 0; t < 64; t++) s += fc1b[t] * fc2w[t * 64 + idx];
        g_bc[idx] = s;
    }
}

// ---------------- segment max over sorted batch ----------------
__global__ void k_segmax(const int* __restrict__ batch, float* __restrict__ ge) {
    int g = blockIdx.x;
    int j = threadIdx.x, ty = threadIdx.y;     // (64,4)
    int lo = 0, hi = NN;
    while (lo < hi) { int m = (lo + hi) >> 1; if (batch[m] < g) lo = m + 1; else hi = m; }
    int start = lo;
    hi = NN;
    while (lo < hi) { int m = (lo + hi) >> 1; if (batch[m] < g + 1) lo = m + 1; else hi = m; }
    int end = lo;
    float mv = -INFINITY;
    for (int r = start + ty; r < end; r += 4)
        mv = fmaxf(mv, g_bufB[r * 64 + j]);
    __shared__ float red[4][64];
    red[ty][j] = mv;
    __syncthreads();
    if (ty == 0) {
        mv = fmaxf(fmaxf(red[0][j], red[1][j]), fmaxf(red[2][j], red[3][j]));
        ge[g * 64 + j] = mv;
    }
}

__global__ void k_logits(const float* __restrict__ ge, const float* __restrict__ w,
                         const float* __restrict__ b, float* __restrict__ out) {
    int g = threadIdx.x;
    if (g < GG) {
        float l0 = b[0], l1 = b[1];
        for (int k = 0; k < 64; k++) {
            float v = ge[g * 64 + k];
            l0 += v * w[k * 2];
            l1 += v * w[k * 2 + 1];
        }
        float m = fmaxf(l0, l1);
        float lse = m + logf(expf(l0 - m) + expf(l1 - m));
        out[g * 2]     = l0 - lse;
        out[g * 2 + 1] = l1 - lse;
    }
}

// ---------------- launch ----------------
extern "C" void kernel_launch(void* const* d_in, const int* in_sizes, int n_in,
                              void* d_out, int out_size) {
    const float* x      = (const float*)d_in[0];
    const int*   ei     = (const int*)d_in[1];
    const int*   batch  = (const int*)d_in[2];
    const float* conv_w = (const float*)d_in[3];
    const float* conv_b = (const float*)d_in[4];
    const float* bn_g   = (const float*)d_in[5];
    const float* bn_b   = (const float*)d_in[6];
    const float* fc1w   = (const float*)d_in[7];
    const float* fc1b   = (const float*)d_in[8];
    const float* fc2w   = (const float*)d_in[9];
    const float* fc2b   = (const float*)d_in[10];
    const float* fc3w   = (const float*)d_in[11];
    const float* fc3b   = (const float*)d_in[12];

    float* out     = (float*)d_out;
    float* emb_out = out;                         // [N,64]
    float* ge_out  = out + (size_t)NN * 64;       // [G,64]
    float* logits  = ge_out + (size_t)GG * 64;    // [G,2]

    const int NB_N = (NN + 255) / 256;            // 391
    const int NB_E = (EE + 255) / 256;            // 4688
    dim3 b64x4(64, 4);

    k_init<<<NB_N, 256>>>();
    k_hist<<<NB_E, 256>>>(ei);
    k_scan1<<<NB_N, 256>>>();
    k_scan2<<<1, 512>>>(NB_N);
    k_scan3<<<NB_N, 256>>>();
    k_fill<<<NB_E, 256>>>(ei);
    k_combine<<<16, 256>>>(fc1w, fc1b, fc2w, fc2b);

    for (int l = 0; l < 3; l++) {
        // bufB = dinv * (act(h) @ W_l)   (act = BN+relu of prev layer; id for l=0)
        k_gemm<<<592, b64x4>>>(x, conv_w + l * 4096, (l == 0) ? 1 : 0, 0, (l > 0) ? 1 : 0, 1, nullptr);
        k_bnzero<<<1, 64>>>();
        // bufA = dinv[d] * (sum hS + hS_self) + b_l ; accumulate BN stats
        k_agg<<<1184, 256>>>(conv_b + l * 64);
        k_bnfinal<<<1, 64>>>(bn_g + l * 64, bn_b + l * 64);
    }
    // bufB = act(bufA) @ (fc1@fc2) + bc ; also writes node_embeddings = act(bufA)
    k_gemm<<<592, b64x4>>>(x, nullptr, 0, 1, 1, 0, emb_out);
    k_segmax<<<GG, b64x4>>>(batch, ge_out);
    k_logits<<<1, 128>>>(ge_out, fc3w, fc3b, logits);
}